// round 3
// baseline (speedup 1.0000x reference)
#include <cuda_runtime.h>
#include <math.h>

#define EMBED  1024
#define NHEADS 16
#define HDIM   64
#define VOCAB  4096
#define BATCH  2
#define SQL    1024
#define SKVL   2048

// Scratch (allocation-free: __device__ globals). ~48 MB total.
__device__ __align__(16) float g_Q [BATCH * SQL  * EMBED];
__device__ __align__(16) float g_K [BATCH * SKVL * EMBED];
__device__ __align__(16) float g_V [BATCH * SKVL * EMBED];
__device__ __align__(16) float g_AO[BATCH * SQL  * EMBED];

// ---------------------------------------------------------------------------
// SGEMM: C[M,N] = A[M,K] @ B[K,N] + bias[N], all row-major fp32.
// Block tile 128x128, K-tile 8, 256 threads, 8x8 per-thread microtile.
// Register prefetch of next K-tile overlaps global latency with FFMA.
// Assumes M%128==0, N%128==0, K%8==0 (true for all call sites here).
// ---------------------------------------------------------------------------
__global__ __launch_bounds__(256) void sgemm_bias(
    const float* __restrict__ A, const float* __restrict__ B,
    const float* __restrict__ bias, float* __restrict__ C,
    int M, int N, int K)
{
    __shared__ float As[8][132];   // transposed A tile: As[k][m], padded
    __shared__ float Bs[8][132];   // Bs[k][n], padded

    const int tid  = threadIdx.x;
    const int m0   = blockIdx.y * 128;
    const int n0   = blockIdx.x * 128;
    const int warp = tid >> 5;
    const int lane = tid & 31;
    // warp grid 4x2 (m x n), lane grid 4x8 (m x n), 8x8 microtile
    const int tm = (warp & 3) * 32 + (lane & 3) * 8;
    const int tn = (warp >> 2) * 64 + (lane >> 2) * 8;

    float acc[8][8];
#pragma unroll
    for (int i = 0; i < 8; ++i)
#pragma unroll
        for (int j = 0; j < 8; ++j) acc[i][j] = 0.f;

    const int arow = tid >> 1;           // 0..127
    const int acol = (tid & 1) * 4;      // 0 or 4
    const int brow = tid >> 5;           // 0..7
    const int bcol = (tid & 31) * 4;     // 0..124

    const float* Ag = A + (size_t)(m0 + arow) * K + acol;
    const float* Bg = B + (size_t)brow * N + n0 + bcol;

    float4 aR = *(const float4*)Ag;
    float4 bR = *(const float4*)Bg;

    const int nk = K >> 3;
    for (int kt = 0; kt < nk; ++kt) {
        // stage current tile into smem (A transposed)
        As[acol + 0][arow] = aR.x;
        As[acol + 1][arow] = aR.y;
        As[acol + 2][arow] = aR.z;
        As[acol + 3][arow] = aR.w;
        *(float4*)&Bs[brow][bcol] = bR;
        __syncthreads();

        // prefetch next tile while computing this one
        if (kt + 1 < nk) {
            aR = *(const float4*)(Ag + (size_t)(kt + 1) * 8);
            bR = *(const float4*)(Bg + (size_t)(kt + 1) * 8 * N);
        }

#pragma unroll
        for (int k = 0; k < 8; ++k) {
            float4 a0 = *(float4*)&As[k][tm];
            float4 a1 = *(float4*)&As[k][tm + 4];
            float4 b0 = *(float4*)&Bs[k][tn];
            float4 b1 = *(float4*)&Bs[k][tn + 4];
            float av[8] = {a0.x, a0.y, a0.z, a0.w, a1.x, a1.y, a1.z, a1.w};
            float bv[8] = {b0.x, b0.y, b0.z, b0.w, b1.x, b1.y, b1.z, b1.w};
#pragma unroll
            for (int i = 0; i < 8; ++i)
#pragma unroll
                for (int j = 0; j < 8; ++j)
                    acc[i][j] = fmaf(av[i], bv[j], acc[i][j]);
        }
        __syncthreads();
    }

    float bb[8];
#pragma unroll
    for (int j = 0; j < 8; ++j) bb[j] = bias[n0 + tn + j];

#pragma unroll
    for (int i = 0; i < 8; ++i) {
        float* Crow = C + (size_t)(m0 + tm + i) * N + n0 + tn;
        float4 o0 = make_float4(acc[i][0] + bb[0], acc[i][1] + bb[1],
                                acc[i][2] + bb[2], acc[i][3] + bb[3]);
        float4 o1 = make_float4(acc[i][4] + bb[4], acc[i][5] + bb[5],
                                acc[i][6] + bb[6], acc[i][7] + bb[7]);
        *(float4*)Crow       = o0;
        *(float4*)(Crow + 4) = o1;
    }
}

// ---------------------------------------------------------------------------
// Flash attention (fp32): per block = one (b,h) and 64 q-rows.
// Streams KV in chunks of 64 rows; never materializes scores to HBM.
// Thread grid 16x16, 4x4 microtiles for both QK^T and AV.
// Smem tiles stored d-major (transposed) so inner products use float4 rows.
// ---------------------------------------------------------------------------
#define FPITCH 68   // multiple of 4 (float4 alignment), 68%32==4 (bank spread)
#define FLASH_SMEM_BYTES (4 * 64 * FPITCH * 4)

__global__ __launch_bounds__(256) void flash_attn()
{
    extern __shared__ float sm[];
    float* Qt = sm;                   // [d=64][r=64]  (pitch 68)
    float* Kt = Qt + 64 * FPITCH;     // [d=64][c=64]
    float* Pt = Kt + 64 * FPITCH;     // [c=64][r=64]
    float* Vs = Pt + 64 * FPITCH;     // [c=64][d=64]

    const int tid = threadIdx.x;
    const int tx  = tid & 15;         // col group
    const int ty  = tid >> 4;         // row group
    const int b   = blockIdx.y >> 4;
    const int h   = blockIdx.y & 15;
    const int q0  = blockIdx.x * 64;

    const float* Qg = g_Q + (size_t)(b * SQL  + q0) * EMBED + h * HDIM;
    const float* Kg = g_K + (size_t)(b * SKVL)      * EMBED + h * HDIM;
    const float* Vg = g_V + (size_t)(b * SKVL)      * EMBED + h * HDIM;

    // Load Q tile transposed: Qt[d][r]
#pragma unroll
    for (int rr = 0; rr < 4; ++rr) {
        int r = rr * 16 + ty;
        float4 q = *(const float4*)(Qg + (size_t)r * EMBED + tx * 4);
        Qt[(tx * 4 + 0) * FPITCH + r] = q.x;
        Qt[(tx * 4 + 1) * FPITCH + r] = q.y;
        Qt[(tx * 4 + 2) * FPITCH + r] = q.z;
        Qt[(tx * 4 + 3) * FPITCH + r] = q.w;
    }

    float m_[4], l_[4], O_[4][4];
#pragma unroll
    for (int i = 0; i < 4; ++i) {
        m_[i] = -1e30f;
        l_[i] = 0.f;
#pragma unroll
        for (int j = 0; j < 4; ++j) O_[i][j] = 0.f;
    }

    const float scale = 0.125f;  // HDIM^-0.5

    for (int ch = 0; ch < SKVL / 64; ++ch) {
        __syncthreads();  // previous chunk fully consumed (also covers Qt init)

        // Load K chunk transposed (Kt[d][c]) and V chunk natural (Vs[c][d])
#pragma unroll
        for (int rr = 0; rr < 4; ++rr) {
            int c = rr * 16 + ty;
            float4 kv = *(const float4*)(Kg + (size_t)(ch * 64 + c) * EMBED + tx * 4);
            Kt[(tx * 4 + 0) * FPITCH + c] = kv.x;
            Kt[(tx * 4 + 1) * FPITCH + c] = kv.y;
            Kt[(tx * 4 + 2) * FPITCH + c] = kv.z;
            Kt[(tx * 4 + 3) * FPITCH + c] = kv.w;
            float4 vv = *(const float4*)(Vg + (size_t)(ch * 64 + c) * EMBED + tx * 4);
            *(float4*)&Vs[c * FPITCH + tx * 4] = vv;
        }
        __syncthreads();

        // S = scale * Q K^T   (4x4 microtile, contraction over d)
        float s[4][4];
#pragma unroll
        for (int i = 0; i < 4; ++i)
#pragma unroll
            for (int j = 0; j < 4; ++j) s[i][j] = 0.f;

#pragma unroll 16
        for (int d = 0; d < 64; ++d) {
            float4 qa = *(float4*)&Qt[d * FPITCH + ty * 4];
            float4 ka = *(float4*)&Kt[d * FPITCH + tx * 4];
            float qv[4] = {qa.x, qa.y, qa.z, qa.w};
            float kv[4] = {ka.x, ka.y, ka.z, ka.w};
#pragma unroll
            for (int i = 0; i < 4; ++i)
#pragma unroll
                for (int j = 0; j < 4; ++j)
                    s[i][j] = fmaf(qv[i], kv[j], s[i][j]);
        }

        // scale + row max (reduce across the 16 tx lanes of each row group)
        float rm[4];
#pragma unroll
        for (int i = 0; i < 4; ++i) {
            s[i][0] *= scale; s[i][1] *= scale; s[i][2] *= scale; s[i][3] *= scale;
            rm[i] = fmaxf(fmaxf(s[i][0], s[i][1]), fmaxf(s[i][2], s[i][3]));
        }
#pragma unroll
        for (int off = 8; off >= 1; off >>= 1)
#pragma unroll
            for (int i = 0; i < 4; ++i)
                rm[i] = fmaxf(rm[i], __shfl_xor_sync(0xffffffffu, rm[i], off));

        float rs[4];
#pragma unroll
        for (int i = 0; i < 4; ++i) {
            float mn = fmaxf(m_[i], rm[i]);
            float al = __expf(m_[i] - mn);
            m_[i] = mn;
#pragma unroll
            for (int j = 0; j < 4; ++j) {
                s[i][j] = __expf(s[i][j] - mn);
                O_[i][j] *= al;
            }
            rs[i] = (s[i][0] + s[i][1]) + (s[i][2] + s[i][3]);
            l_[i] = l_[i] * al;
        }
#pragma unroll
        for (int off = 8; off >= 1; off >>= 1)
#pragma unroll
            for (int i = 0; i < 4; ++i)
                rs[i] += __shfl_xor_sync(0xffffffffu, rs[i], off);
#pragma unroll
        for (int i = 0; i < 4; ++i) l_[i] += rs[i];

        // Store P transposed: Pt[c][r]
#pragma unroll
        for (int j = 0; j < 4; ++j)
#pragma unroll
            for (int i = 0; i < 4; ++i)
                Pt[(tx * 4 + j) * FPITCH + ty * 4 + i] = s[i][j];
        __syncthreads();

        // O += P @ V  (contraction over c)
#pragma unroll 8
        for (int c = 0; c < 64; ++c) {
            float4 pa = *(float4*)&Pt[c * FPITCH + ty * 4];
            float4 va = *(float4*)&Vs[c * FPITCH + tx * 4];
            float pv[4] = {pa.x, pa.y, pa.z, pa.w};
            float vv[4] = {va.x, va.y, va.z, va.w};
#pragma unroll
            for (int i = 0; i < 4; ++i)
#pragma unroll
                for (int j = 0; j < 4; ++j)
                    O_[i][j] = fmaf(pv[i], vv[j], O_[i][j]);
        }
    }

    // Normalize and write out (g_AO[b*SQL+q][h*64+d])
    float* Og = g_AO + (size_t)(b * SQL + q0) * EMBED + h * HDIM;
#pragma unroll
    for (int i = 0; i < 4; ++i) {
        float inv = 1.f / l_[i];
        float4 o = make_float4(O_[i][0] * inv, O_[i][1] * inv,
                               O_[i][2] * inv, O_[i][3] * inv);
        *(float4*)(Og + (size_t)(ty * 4 + i) * EMBED + tx * 4) = o;
    }
}

// ---------------------------------------------------------------------------
// Launch: x,context,Wq,bq,Wk,bk,Wv,bv,Wp,bp  -> out [2,1024,4096] fp32
// ---------------------------------------------------------------------------
extern "C" void kernel_launch(void* const* d_in, const int* in_sizes, int n_in,
                              void* d_out, int out_size)
{
    const float* x   = (const float*)d_in[0];
    const float* ctx = (const float*)d_in[1];
    const float* Wq  = (const float*)d_in[2];
    const float* bq  = (const float*)d_in[3];
    const float* Wk  = (const float*)d_in[4];
    const float* bk  = (const float*)d_in[5];
    const float* Wv  = (const float*)d_in[6];
    const float* bv  = (const float*)d_in[7];
    const float* Wp  = (const float*)d_in[8];
    const float* bp  = (const float*)d_in[9];
    float* out = (float*)d_out;

    float *Qd, *Kd, *Vd, *AOd;
    cudaGetSymbolAddress((void**)&Qd,  g_Q);
    cudaGetSymbolAddress((void**)&Kd,  g_K);
    cudaGetSymbolAddress((void**)&Vd,  g_V);
    cudaGetSymbolAddress((void**)&AOd, g_AO);

    cudaFuncSetAttribute(flash_attn,
                         cudaFuncAttributeMaxDynamicSharedMemorySize,
                         FLASH_SMEM_BYTES);

    // Q = x @ Wq + bq            [2048,1024]
    sgemm_bias<<<dim3(EMBED / 128, (BATCH * SQL) / 128), 256>>>(
        x, Wq, bq, Qd, BATCH * SQL, EMBED, EMBED);
    // K = context @ Wk + bk      [4096,1024]
    sgemm_bias<<<dim3(EMBED / 128, (BATCH * SKVL) / 128), 256>>>(
        ctx, Wk, bk, Kd, BATCH * SKVL, EMBED, EMBED);
    // V = context @ Wv + bv      [4096,1024]
    sgemm_bias<<<dim3(EMBED / 128, (BATCH * SKVL) / 128), 256>>>(
        ctx, Wv, bv, Vd, BATCH * SKVL, EMBED, EMBED);

    // attention -> g_AO          [2048,1024]
    flash_attn<<<dim3(SQL / 64, BATCH * NHEADS), 256, FLASH_SMEM_BYTES>>>();

    // out = AO @ Wp + bp         [2048,4096]
    sgemm_bias<<<dim3(VOCAB / 128, (BATCH * SQL) / 128), 256>>>(
        AOd, Wp, bp, out, BATCH * SQL, VOCAB, EMBED);
}

// round 5
// speedup vs baseline: 1.3343x; 1.3343x over previous
#include <cuda_runtime.h>
#include <cuda_bf16.h>
#include <math.h>
#include <stdint.h>

#define EMBED  1024
#define NHEADS 16
#define HDIM   64
#define VOCAB  4096
#define BATCH  2
#define SQL    1024
#define SKVL   2048

// ---------------------------------------------------------------------------
// Scratch (allocation-free __device__ globals)
// ---------------------------------------------------------------------------
__device__ __align__(16) float g_Q [BATCH * SQL  * EMBED];
__device__ __align__(16) float g_K [BATCH * SKVL * EMBED];
__device__ __align__(16) float g_V [BATCH * SKVL * EMBED];
__device__ __align__(16) float g_AO[BATCH * SQL  * EMBED];

// bf16 split operands (hi + lo) for the tensor-core GEMMs
__device__ __align__(16) __nv_bfloat16 g_xh [BATCH * SQL  * EMBED];
__device__ __align__(16) __nv_bfloat16 g_xl [BATCH * SQL  * EMBED];
__device__ __align__(16) __nv_bfloat16 g_ch [BATCH * SKVL * EMBED];
__device__ __align__(16) __nv_bfloat16 g_cl [BATCH * SKVL * EMBED];
__device__ __align__(16) __nv_bfloat16 g_aoh[BATCH * SQL  * EMBED];
__device__ __align__(16) __nv_bfloat16 g_aol[BATCH * SQL  * EMBED];
__device__ __align__(16) __nv_bfloat16 g_WqTh[EMBED * EMBED];
__device__ __align__(16) __nv_bfloat16 g_WqTl[EMBED * EMBED];
__device__ __align__(16) __nv_bfloat16 g_WkTh[EMBED * EMBED];
__device__ __align__(16) __nv_bfloat16 g_WkTl[EMBED * EMBED];
__device__ __align__(16) __nv_bfloat16 g_WvTh[EMBED * EMBED];
__device__ __align__(16) __nv_bfloat16 g_WvTl[EMBED * EMBED];
__device__ __align__(16) __nv_bfloat16 g_WpTh[VOCAB * EMBED];
__device__ __align__(16) __nv_bfloat16 g_WpTl[VOCAB * EMBED];

// ---------------------------------------------------------------------------
// Helpers
// ---------------------------------------------------------------------------
__device__ __forceinline__ uint32_t smem_u32(const void* p) {
    uint32_t a;
    asm("{ .reg .u64 t; cvta.to.shared.u64 t, %1; cvt.u32.u64 %0, t; }"
        : "=r"(a) : "l"(p));
    return a;
}
__device__ __forceinline__ void cpasync16(uint32_t dst, const void* src) {
    asm volatile("cp.async.cg.shared.global [%0], [%1], 16;"
                 :: "r"(dst), "l"(src) : "memory");
}
#define CP_COMMIT() asm volatile("cp.async.commit_group;" ::: "memory")
#define CP_WAIT(N)  asm volatile("cp.async.wait_group %0;" :: "n"(N) : "memory")

__device__ __forceinline__ void mma16816(float* c, const uint32_t* a, const uint32_t* b) {
    asm volatile(
        "mma.sync.aligned.m16n8k16.row.col.f32.bf16.bf16.f32 "
        "{%0,%1,%2,%3}, {%4,%5,%6,%7}, {%8,%9}, {%0,%1,%2,%3};"
        : "+f"(c[0]), "+f"(c[1]), "+f"(c[2]), "+f"(c[3])
        : "r"(a[0]), "r"(a[1]), "r"(a[2]), "r"(a[3]), "r"(b[0]), "r"(b[1]));
}

__device__ __forceinline__ void split1(float v, __nv_bfloat16& h, __nv_bfloat16& l) {
    h = __float2bfloat16_rn(v);
    l = __float2bfloat16_rn(v - __bfloat162float(h));
}

// ---------------------------------------------------------------------------
// Elementwise fp32 -> bf16 hi/lo split (vectorized, n multiple of 4)
// ---------------------------------------------------------------------------
__global__ __launch_bounds__(256) void split_f32(
    const float4* __restrict__ in,
    __nv_bfloat16* __restrict__ hi, __nv_bfloat16* __restrict__ lo, int n4)
{
    int i = blockIdx.x * 256 + threadIdx.x;
    if (i >= n4) return;
    float4 v = in[i];
    __nv_bfloat16 h[4], l[4];
    split1(v.x, h[0], l[0]); split1(v.y, h[1], l[1]);
    split1(v.z, h[2], l[2]); split1(v.w, h[3], l[3]);
    *(uint2*)&hi[i * 4] = *(uint2*)h;
    *(uint2*)&lo[i * 4] = *(uint2*)l;
}

// ---------------------------------------------------------------------------
// Weight transpose + split: WhiT/WloT[n][k] = split(W[k][n])
// ---------------------------------------------------------------------------
__global__ void transpose_split(const float* __restrict__ W,
                                __nv_bfloat16* __restrict__ WhT,
                                __nv_bfloat16* __restrict__ WlT,
                                int K, int N)
{
    __shared__ float t[32][33];
    int n  = blockIdx.x * 32 + threadIdx.x;
    int k0 = blockIdx.y * 32;
    for (int j = threadIdx.y; j < 32; j += 8)
        t[j][threadIdx.x] = W[(size_t)(k0 + j) * N + n];
    __syncthreads();
    int k  = blockIdx.y * 32 + threadIdx.x;
    int n0 = blockIdx.x * 32;
    for (int j = threadIdx.y; j < 32; j += 8) {
        float v = t[threadIdx.x][j];
        __nv_bfloat16 h, l;
        split1(v, h, l);
        WhT[(size_t)(n0 + j) * K + k] = h;
        WlT[(size_t)(n0 + j) * K + k] = l;
    }
}

// ---------------------------------------------------------------------------
// bf16x3 GEMM: C[M,N] = Ah/Al [M][K] @ (Bh/Bl [N][K])^T + bias[N]
// using D += Ah*Bh + Ah*Bl + Al*Bh with fp32 mma accumulators.
// CTA 128x128, k-tile 32, 256 threads (8 warps: 2(m) x 4(n), warp tile 64x32),
// cp.async double-buffered smem, 80-byte row pitch (conflict-free frag loads).
// ---------------------------------------------------------------------------
#define PITCH_B   80                      // bytes per 32-elem bf16 row (padded)
#define TILE_B    (128 * PITCH_B)         // 10240 B per operand tile
#define OFF_AHI   0
#define OFF_ALO   (TILE_B)
#define OFF_BHI   (2 * TILE_B)
#define OFF_BLO   (3 * TILE_B)
#define BUF_B     (4 * TILE_B)            // 40960 B per stage
#define GEMM_SMEM (2 * BUF_B)             // 81920 B

__global__ __launch_bounds__(256) void gemm_bf16x3(
    const __nv_bfloat16* __restrict__ Ah, const __nv_bfloat16* __restrict__ Al,
    const __nv_bfloat16* __restrict__ Bh, const __nv_bfloat16* __restrict__ Bl,
    const float* __restrict__ bias, float* __restrict__ C,
    int M, int N, int K)
{
    extern __shared__ char smem[];
    const uint32_t sbase = smem_u32(smem);

    const int tid  = threadIdx.x;
    const int wid  = tid >> 5;
    const int lane = tid & 31;
    const int wm   = wid & 1;             // 0..1 (64-row halves)
    const int wn   = wid >> 1;            // 0..3 (32-col quarters)
    const int lr   = lane >> 2;           // 0..7
    const int lc   = lane & 3;            // 0..3

    const int m0 = blockIdx.y * 128;
    const int n0 = blockIdx.x * 128;

    // loader mapping: 512 16B-chunks per operand tile; 2 chunks/thread
    const int lrow0 = tid >> 2;           // chunk j=0: rows 0..63
    const int lcc0  = tid & 3;
    // chunk j=1: rows 64..127, same col pattern

    const size_t aBase = (size_t)m0 * K;
    const size_t bBase = (size_t)n0 * K;

    auto load_tile = [&](int buf, int kt) {
        uint32_t sb = sbase + buf * BUF_B;
        const size_t gk = (size_t)kt * 32;
#pragma unroll
        for (int j = 0; j < 2; ++j) {
            int row = lrow0 + j * 64;
            int cc  = lcc0;
            uint32_t soff = (uint32_t)(row * PITCH_B + cc * 16);
            size_t   goff = aBase + (size_t)row * K + gk + cc * 8;
            cpasync16(sb + OFF_AHI + soff, Ah + goff);
            cpasync16(sb + OFF_ALO + soff, Al + goff);
            size_t   goffb = bBase + (size_t)row * K + gk + cc * 8;
            cpasync16(sb + OFF_BHI + soff, Bh + goffb);
            cpasync16(sb + OFF_BLO + soff, Bl + goffb);
        }
        CP_COMMIT();
    };

    float acc[4][4][4];
#pragma unroll
    for (int i = 0; i < 4; ++i)
#pragma unroll
        for (int j = 0; j < 4; ++j)
#pragma unroll
            for (int r = 0; r < 4; ++r) acc[i][j][r] = 0.f;

    // per-thread fragment base byte offsets within a tile
    const uint32_t aRB = (uint32_t)((wm * 64 + lr) * PITCH_B + lc * 4);
    const uint32_t bRB = (uint32_t)((wn * 32 + lr) * PITCH_B + lc * 4);

    load_tile(0, 0);

    const int nk = K >> 5;
    for (int kt = 0; kt < nk; ++kt) {
        const int cur = kt & 1;
        if (kt + 1 < nk) { load_tile(cur ^ 1, kt + 1); CP_WAIT(1); }
        else             { CP_WAIT(0); }
        __syncthreads();

        const char* Sa_h = smem + cur * BUF_B + OFF_AHI;
        const char* Sa_l = smem + cur * BUF_B + OFF_ALO;
        const char* Sb_h = smem + cur * BUF_B + OFF_BHI;
        const char* Sb_l = smem + cur * BUF_B + OFF_BLO;

#pragma unroll
        for (int ks = 0; ks < 2; ++ks) {
            const uint32_t ko = (uint32_t)(ks * 32);

            uint32_t ahi[4][4];
#pragma unroll
            for (int mi = 0; mi < 4; ++mi) {
                uint32_t o = aRB + mi * (16 * PITCH_B) + ko;
                ahi[mi][0] = *(const uint32_t*)(Sa_h + o);
                ahi[mi][1] = *(const uint32_t*)(Sa_h + o + 8 * PITCH_B);
                ahi[mi][2] = *(const uint32_t*)(Sa_h + o + 16);
                ahi[mi][3] = *(const uint32_t*)(Sa_h + o + 8 * PITCH_B + 16);
            }
            uint32_t bhi[4][2];
#pragma unroll
            for (int ni = 0; ni < 4; ++ni) {
                uint32_t o = bRB + ni * (8 * PITCH_B) + ko;
                bhi[ni][0] = *(const uint32_t*)(Sb_h + o);
                bhi[ni][1] = *(const uint32_t*)(Sb_h + o + 16);
            }
#pragma unroll
            for (int mi = 0; mi < 4; ++mi)
#pragma unroll
                for (int ni = 0; ni < 4; ++ni)
                    mma16816(acc[mi][ni], ahi[mi], bhi[ni]);

            uint32_t blo[4][2];
#pragma unroll
            for (int ni = 0; ni < 4; ++ni) {
                uint32_t o = bRB + ni * (8 * PITCH_B) + ko;
                blo[ni][0] = *(const uint32_t*)(Sb_l + o);
                blo[ni][1] = *(const uint32_t*)(Sb_l + o + 16);
            }
#pragma unroll
            for (int mi = 0; mi < 4; ++mi)
#pragma unroll
                for (int ni = 0; ni < 4; ++ni)
                    mma16816(acc[mi][ni], ahi[mi], blo[ni]);

            uint32_t alo[4][4];
#pragma unroll
            for (int mi = 0; mi < 4; ++mi) {
                uint32_t o = aRB + mi * (16 * PITCH_B) + ko;
                alo[mi][0] = *(const uint32_t*)(Sa_l + o);
                alo[mi][1] = *(const uint32_t*)(Sa_l + o + 8 * PITCH_B);
                alo[mi][2] = *(const uint32_t*)(Sa_l + o + 16);
                alo[mi][3] = *(const uint32_t*)(Sa_l + o + 8 * PITCH_B + 16);
            }
#pragma unroll
            for (int mi = 0; mi < 4; ++mi)
#pragma unroll
                for (int ni = 0; ni < 4; ++ni)
                    mma16816(acc[mi][ni], alo[mi], bhi[ni]);
        }
        __syncthreads();
    }

    // Epilogue: acc layout c0,c1 @ (row, col+{0,1}); c2,c3 @ (row+8, ...)
#pragma unroll
    for (int mi = 0; mi < 4; ++mi) {
        int r = m0 + wm * 64 + mi * 16 + lr;
#pragma unroll
        for (int ni = 0; ni < 4; ++ni) {
            int c = n0 + wn * 32 + ni * 8 + lc * 2;
            float b0 = __ldg(bias + c), b1 = __ldg(bias + c + 1);
            float2 o0 = make_float2(acc[mi][ni][0] + b0, acc[mi][ni][1] + b1);
            float2 o1 = make_float2(acc[mi][ni][2] + b0, acc[mi][ni][3] + b1);
            *(float2*)&C[(size_t)r * N + c]       = o0;
            *(float2*)&C[(size_t)(r + 8) * N + c] = o1;
        }
    }
}

// ---------------------------------------------------------------------------
// Flash attention (fp32): UNCHANGED from the passing round-3 kernel (609us).
// ---------------------------------------------------------------------------
#define FPITCH 68
#define FLASH_SMEM_BYTES (4 * 64 * FPITCH * 4)

__global__ __launch_bounds__(256) void flash_attn()
{
    extern __shared__ float sm[];
    float* Qt = sm;
    float* Kt = Qt + 64 * FPITCH;
    float* Pt = Kt + 64 * FPITCH;
    float* Vs = Pt + 64 * FPITCH;

    const int tid = threadIdx.x;
    const int tx  = tid & 15;
    const int ty  = tid >> 4;
    const int b   = blockIdx.y >> 4;
    const int h   = blockIdx.y & 15;
    const int q0  = blockIdx.x * 64;

    const float* Qg = g_Q + (size_t)(b * SQL  + q0) * EMBED + h * HDIM;
    const float* Kg = g_K + (size_t)(b * SKVL)      * EMBED + h * HDIM;
    const float* Vg = g_V + (size_t)(b * SKVL)      * EMBED + h * HDIM;

#pragma unroll
    for (int rr = 0; rr < 4; ++rr) {
        int r = rr * 16 + ty;
        float4 q = *(const float4*)(Qg + (size_t)r * EMBED + tx * 4);
        Qt[(tx * 4 + 0) * FPITCH + r] = q.x;
        Qt[(tx * 4 + 1) * FPITCH + r] = q.y;
        Qt[(tx * 4 + 2) * FPITCH + r] = q.z;
        Qt[(tx * 4 + 3) * FPITCH + r] = q.w;
    }

    float m_[4], l_[4], O_[4][4];
#pragma unroll
    for (int i = 0; i < 4; ++i) {
        m_[i] = -1e30f;
        l_[i] = 0.f;
#pragma unroll
        for (int j = 0; j < 4; ++j) O_[i][j] = 0.f;
    }

    const float scale = 0.125f;

    for (int ch = 0; ch < SKVL / 64; ++ch) {
        __syncthreads();

#pragma unroll
        for (int rr = 0; rr < 4; ++rr) {
            int c = rr * 16 + ty;
            float4 kv = *(const float4*)(Kg + (size_t)(ch * 64 + c) * EMBED + tx * 4);
            Kt[(tx * 4 + 0) * FPITCH + c] = kv.x;
            Kt[(tx * 4 + 1) * FPITCH + c] = kv.y;
            Kt[(tx * 4 + 2) * FPITCH + c] = kv.z;
            Kt[(tx * 4 + 3) * FPITCH + c] = kv.w;
            float4 vv = *(const float4*)(Vg + (size_t)(ch * 64 + c) * EMBED + tx * 4);
            *(float4*)&Vs[c * FPITCH + tx * 4] = vv;
        }
        __syncthreads();

        float s[4][4];
#pragma unroll
        for (int i = 0; i < 4; ++i)
#pragma unroll
            for (int j = 0; j < 4; ++j) s[i][j] = 0.f;

#pragma unroll 16
        for (int d = 0; d < 64; ++d) {
            float4 qa = *(float4*)&Qt[d * FPITCH + ty * 4];
            float4 ka = *(float4*)&Kt[d * FPITCH + tx * 4];
            float qv[4] = {qa.x, qa.y, qa.z, qa.w};
            float kv[4] = {ka.x, ka.y, ka.z, ka.w};
#pragma unroll
            for (int i = 0; i < 4; ++i)
#pragma unroll
                for (int j = 0; j < 4; ++j)
                    s[i][j] = fmaf(qv[i], kv[j], s[i][j]);
        }

        float rm[4];
#pragma unroll
        for (int i = 0; i < 4; ++i) {
            s[i][0] *= scale; s[i][1] *= scale; s[i][2] *= scale; s[i][3] *= scale;
            rm[i] = fmaxf(fmaxf(s[i][0], s[i][1]), fmaxf(s[i][2], s[i][3]));
        }
#pragma unroll
        for (int off = 8; off >= 1; off >>= 1)
#pragma unroll
            for (int i = 0; i < 4; ++i)
                rm[i] = fmaxf(rm[i], __shfl_xor_sync(0xffffffffu, rm[i], off));

        float rs[4];
#pragma unroll
        for (int i = 0; i < 4; ++i) {
            float mn = fmaxf(m_[i], rm[i]);
            float al = __expf(m_[i] - mn);
            m_[i] = mn;
#pragma unroll
            for (int j = 0; j < 4; ++j) {
                s[i][j] = __expf(s[i][j] - mn);
                O_[i][j] *= al;
            }
            rs[i] = (s[i][0] + s[i][1]) + (s[i][2] + s[i][3]);
            l_[i] = l_[i] * al;
        }
#pragma unroll
        for (int off = 8; off >= 1; off >>= 1)
#pragma unroll
            for (int i = 0; i < 4; ++i)
                rs[i] += __shfl_xor_sync(0xffffffffu, rs[i], off);
#pragma unroll
        for (int i = 0; i < 4; ++i) l_[i] += rs[i];

#pragma unroll
        for (int j = 0; j < 4; ++j)
#pragma unroll
            for (int i = 0; i < 4; ++i)
                Pt[(tx * 4 + j) * FPITCH + ty * 4 + i] = s[i][j];
        __syncthreads();

#pragma unroll 8
        for (int c = 0; c < 64; ++c) {
            float4 pa = *(float4*)&Pt[c * FPITCH + ty * 4];
            float4 va = *(float4*)&Vs[c * FPITCH + tx * 4];
            float pv[4] = {pa.x, pa.y, pa.z, pa.w};
            float vv[4] = {va.x, va.y, va.z, va.w};
#pragma unroll
            for (int i = 0; i < 4; ++i)
#pragma unroll
                for (int j = 0; j < 4; ++j)
                    O_[i][j] = fmaf(pv[i], vv[j], O_[i][j]);
        }
    }

    float* Og = g_AO + (size_t)(b * SQL + q0) * EMBED + h * HDIM;
#pragma unroll
    for (int i = 0; i < 4; ++i) {
        float inv = 1.f / l_[i];
        float4 o = make_float4(O_[i][0] * inv, O_[i][1] * inv,
                               O_[i][2] * inv, O_[i][3] * inv);
        *(float4*)(Og + (size_t)(ty * 4 + i) * EMBED + tx * 4) = o;
    }
}

// ---------------------------------------------------------------------------
// Launch
// ---------------------------------------------------------------------------
extern "C" void kernel_launch(void* const* d_in, const int* in_sizes, int n_in,
                              void* d_out, int out_size)
{
    const float* x   = (const float*)d_in[0];
    const float* ctx = (const float*)d_in[1];
    const float* Wq  = (const float*)d_in[2];
    const float* bq  = (const float*)d_in[3];
    const float* Wk  = (const float*)d_in[4];
    const float* bk  = (const float*)d_in[5];
    const float* Wv  = (const float*)d_in[6];
    const float* bv  = (const float*)d_in[7];
    const float* Wp  = (const float*)d_in[8];
    const float* bp  = (const float*)d_in[9];
    float* out = (float*)d_out;

    float *Qd, *Kd, *Vd, *AOd;
    __nv_bfloat16 *xh, *xl, *ch_, *cl_, *aoh, *aol;
    __nv_bfloat16 *WqTh, *WqTl, *WkTh, *WkTl, *WvTh, *WvTl, *WpTh, *WpTl;
    cudaGetSymbolAddress((void**)&Qd,  g_Q);
    cudaGetSymbolAddress((void**)&Kd,  g_K);
    cudaGetSymbolAddress((void**)&Vd,  g_V);
    cudaGetSymbolAddress((void**)&AOd, g_AO);
    cudaGetSymbolAddress((void**)&xh,  g_xh);
    cudaGetSymbolAddress((void**)&xl,  g_xl);
    cudaGetSymbolAddress((void**)&ch_, g_ch);
    cudaGetSymbolAddress((void**)&cl_, g_cl);
    cudaGetSymbolAddress((void**)&aoh, g_aoh);
    cudaGetSymbolAddress((void**)&aol, g_aol);
    cudaGetSymbolAddress((void**)&WqTh, g_WqTh);
    cudaGetSymbolAddress((void**)&WqTl, g_WqTl);
    cudaGetSymbolAddress((void**)&WkTh, g_WkTh);
    cudaGetSymbolAddress((void**)&WkTl, g_WkTl);
    cudaGetSymbolAddress((void**)&WvTh, g_WvTh);
    cudaGetSymbolAddress((void**)&WvTl, g_WvTl);
    cudaGetSymbolAddress((void**)&WpTh, g_WpTh);
    cudaGetSymbolAddress((void**)&WpTl, g_WpTl);

    cudaFuncSetAttribute(flash_attn, cudaFuncAttributeMaxDynamicSharedMemorySize,
                         FLASH_SMEM_BYTES);
    cudaFuncSetAttribute(gemm_bf16x3, cudaFuncAttributeMaxDynamicSharedMemorySize,
                         GEMM_SMEM);

    const int NX  = BATCH * SQL  * EMBED;   // x / AO elems
    const int NC  = BATCH * SKVL * EMBED;   // ctx elems

    // Split activations and weights into bf16 hi/lo
    split_f32<<<(NX / 4 + 255) / 256, 256>>>((const float4*)x,   xh,  xl,  NX / 4);
    split_f32<<<(NC / 4 + 255) / 256, 256>>>((const float4*)ctx, ch_, cl_, NC / 4);
    transpose_split<<<dim3(EMBED / 32, EMBED / 32), dim3(32, 8)>>>(Wq, WqTh, WqTl, EMBED, EMBED);
    transpose_split<<<dim3(EMBED / 32, EMBED / 32), dim3(32, 8)>>>(Wk, WkTh, WkTl, EMBED, EMBED);
    transpose_split<<<dim3(EMBED / 32, EMBED / 32), dim3(32, 8)>>>(Wv, WvTh, WvTl, EMBED, EMBED);
    transpose_split<<<dim3(VOCAB / 32, EMBED / 32), dim3(32, 8)>>>(Wp, WpTh, WpTl, EMBED, VOCAB);

    // Projections (bf16x3 tensor-core GEMMs)
    gemm_bf16x3<<<dim3(EMBED / 128, (BATCH * SQL) / 128), 256, GEMM_SMEM>>>(
        xh, xl, WqTh, WqTl, bq, Qd, BATCH * SQL, EMBED, EMBED);
    gemm_bf16x3<<<dim3(EMBED / 128, (BATCH * SKVL) / 128), 256, GEMM_SMEM>>>(
        ch_, cl_, WkTh, WkTl, bk, Kd, BATCH * SKVL, EMBED, EMBED);
    gemm_bf16x3<<<dim3(EMBED / 128, (BATCH * SKVL) / 128), 256, GEMM_SMEM>>>(
        ch_, cl_, WvTh, WvTl, bv, Vd, BATCH * SKVL, EMBED, EMBED);

    // Attention (fp32)
    flash_attn<<<dim3(SQL / 64, BATCH * NHEADS), 256, FLASH_SMEM_BYTES>>>();

    // Split AO, then output projection
    split_f32<<<(NX / 4 + 255) / 256, 256>>>((const float4*)AOd, aoh, aol, NX / 4);
    gemm_bf16x3<<<dim3(VOCAB / 128, (BATCH * SQL) / 128), 256, GEMM_SMEM>>>(
        aoh, aol, WpTh, WpTl, bp, out, BATCH * SQL, VOCAB, EMBED);
}

// round 6
// speedup vs baseline: 2.2550x; 1.6900x over previous
#include <cuda_runtime.h>
#include <cuda_bf16.h>
#include <math.h>
#include <stdint.h>

#define EMBED  1024
#define NHEADS 16
#define HDIM   64
#define VOCAB  4096
#define BATCH  2
#define SQL    1024
#define SKVL   2048

// ---------------------------------------------------------------------------
// Scratch (allocation-free __device__ globals)
// ---------------------------------------------------------------------------
__device__ __align__(16) __nv_bfloat16 g_Qh [BATCH * SQL  * EMBED];
__device__ __align__(16) __nv_bfloat16 g_Ql [BATCH * SQL  * EMBED];
__device__ __align__(16) __nv_bfloat16 g_Kh [BATCH * SKVL * EMBED];
__device__ __align__(16) __nv_bfloat16 g_Kl [BATCH * SKVL * EMBED];
__device__ __align__(16) __nv_bfloat16 g_Vh [BATCH * SKVL * EMBED];
__device__ __align__(16) __nv_bfloat16 g_Vl [BATCH * SKVL * EMBED];
__device__ __align__(16) __nv_bfloat16 g_xh [BATCH * SQL  * EMBED];
__device__ __align__(16) __nv_bfloat16 g_xl [BATCH * SQL  * EMBED];
__device__ __align__(16) __nv_bfloat16 g_ch [BATCH * SKVL * EMBED];
__device__ __align__(16) __nv_bfloat16 g_cl [BATCH * SKVL * EMBED];
__device__ __align__(16) __nv_bfloat16 g_aoh[BATCH * SQL  * EMBED];
__device__ __align__(16) __nv_bfloat16 g_aol[BATCH * SQL  * EMBED];
__device__ __align__(16) __nv_bfloat16 g_WqTh[EMBED * EMBED];
__device__ __align__(16) __nv_bfloat16 g_WqTl[EMBED * EMBED];
__device__ __align__(16) __nv_bfloat16 g_WkTh[EMBED * EMBED];
__device__ __align__(16) __nv_bfloat16 g_WkTl[EMBED * EMBED];
__device__ __align__(16) __nv_bfloat16 g_WvTh[EMBED * EMBED];
__device__ __align__(16) __nv_bfloat16 g_WvTl[EMBED * EMBED];
__device__ __align__(16) __nv_bfloat16 g_WpTh[VOCAB * EMBED];
__device__ __align__(16) __nv_bfloat16 g_WpTl[VOCAB * EMBED];

// ---------------------------------------------------------------------------
// Helpers
// ---------------------------------------------------------------------------
__device__ __forceinline__ uint32_t smem_u32(const void* p) {
    uint32_t a;
    asm("{ .reg .u64 t; cvta.to.shared.u64 t, %1; cvt.u32.u64 %0, t; }"
        : "=r"(a) : "l"(p));
    return a;
}
__device__ __forceinline__ void cpasync16(uint32_t dst, const void* src) {
    asm volatile("cp.async.cg.shared.global [%0], [%1], 16;"
                 :: "r"(dst), "l"(src) : "memory");
}
#define CP_COMMIT() asm volatile("cp.async.commit_group;" ::: "memory")
#define CP_WAIT(N)  asm volatile("cp.async.wait_group %0;" :: "n"(N) : "memory")

__device__ __forceinline__ void mma16816(float* c, const uint32_t* a,
                                         uint32_t b0, uint32_t b1) {
    asm volatile(
        "mma.sync.aligned.m16n8k16.row.col.f32.bf16.bf16.f32 "
        "{%0,%1,%2,%3}, {%4,%5,%6,%7}, {%8,%9}, {%0,%1,%2,%3};"
        : "+f"(c[0]), "+f"(c[1]), "+f"(c[2]), "+f"(c[3])
        : "r"(a[0]), "r"(a[1]), "r"(a[2]), "r"(a[3]), "r"(b0), "r"(b1));
}
__device__ __forceinline__ void ldsm_x4(uint32_t* r, uint32_t addr) {
    asm volatile("ldmatrix.sync.aligned.m8n8.x4.shared.b16 {%0,%1,%2,%3}, [%4];"
                 : "=r"(r[0]), "=r"(r[1]), "=r"(r[2]), "=r"(r[3]) : "r"(addr));
}
__device__ __forceinline__ void ldsm_x4_t(uint32_t* r, uint32_t addr) {
    asm volatile("ldmatrix.sync.aligned.m8n8.x4.trans.shared.b16 {%0,%1,%2,%3}, [%4];"
                 : "=r"(r[0]), "=r"(r[1]), "=r"(r[2]), "=r"(r[3]) : "r"(addr));
}

__device__ __forceinline__ void split1(float v, __nv_bfloat16& h, __nv_bfloat16& l) {
    h = __float2bfloat16_rn(v);
    l = __float2bfloat16_rn(v - __bfloat162float(h));
}
// pack (a,b) -> bf16x2 hi + bf16x2 lo residual (a in low half)
__device__ __forceinline__ void split2(float a, float b, uint32_t& h, uint32_t& l) {
    __nv_bfloat162 hv = __floats2bfloat162_rn(a, b);
    __nv_bfloat162 lv = __floats2bfloat162_rn(a - __bfloat162float(hv.x),
                                              b - __bfloat162float(hv.y));
    h = *(uint32_t*)&hv;
    l = *(uint32_t*)&lv;
}

#define SWZ(off) ((uint32_t)(off) ^ ((((uint32_t)(off)) >> 3) & 0x70u))

// ---------------------------------------------------------------------------
// fp32 -> bf16 hi/lo split (vectorized)
// ---------------------------------------------------------------------------
__global__ __launch_bounds__(256) void split_f32(
    const float4* __restrict__ in,
    __nv_bfloat16* __restrict__ hi, __nv_bfloat16* __restrict__ lo, int n4)
{
    int i = blockIdx.x * 256 + threadIdx.x;
    if (i >= n4) return;
    float4 v = in[i];
    __nv_bfloat16 h[4], l[4];
    split1(v.x, h[0], l[0]); split1(v.y, h[1], l[1]);
    split1(v.z, h[2], l[2]); split1(v.w, h[3], l[3]);
    *(uint2*)&hi[i * 4] = *(uint2*)h;
    *(uint2*)&lo[i * 4] = *(uint2*)l;
}

// ---------------------------------------------------------------------------
// Weight transpose + split
// ---------------------------------------------------------------------------
__global__ void transpose_split(const float* __restrict__ W,
                                __nv_bfloat16* __restrict__ WhT,
                                __nv_bfloat16* __restrict__ WlT,
                                int K, int N)
{
    __shared__ float t[32][33];
    int n  = blockIdx.x * 32 + threadIdx.x;
    int k0 = blockIdx.y * 32;
    for (int j = threadIdx.y; j < 32; j += 8)
        t[j][threadIdx.x] = W[(size_t)(k0 + j) * N + n];
    __syncthreads();
    int k  = blockIdx.y * 32 + threadIdx.x;
    int n0 = blockIdx.x * 32;
    for (int j = threadIdx.y; j < 32; j += 8) {
        float v = t[threadIdx.x][j];
        __nv_bfloat16 h, l;
        split1(v, h, l);
        WhT[(size_t)(n0 + j) * K + k] = h;
        WlT[(size_t)(n0 + j) * K + k] = l;
    }
}

// ---------------------------------------------------------------------------
// bf16x3 GEMM (from round 5, proven): C = Ah/Al @ (Bh/Bl)^T + bias
// SPLIT=true writes bf16 hi/lo outputs (for Q/K/V), else fp32.
// ---------------------------------------------------------------------------
#define PITCH_B   80
#define TILE_B    (128 * PITCH_B)
#define OFF_AHI   0
#define OFF_ALO   (TILE_B)
#define OFF_BHI   (2 * TILE_B)
#define OFF_BLO   (3 * TILE_B)
#define BUF_B     (4 * TILE_B)
#define GEMM_SMEM (2 * BUF_B)

template<bool SPLIT>
__global__ __launch_bounds__(256) void gemm_bf16x3(
    const __nv_bfloat16* __restrict__ Ah, const __nv_bfloat16* __restrict__ Al,
    const __nv_bfloat16* __restrict__ Bh, const __nv_bfloat16* __restrict__ Bl,
    const float* __restrict__ bias, float* __restrict__ C,
    __nv_bfloat16* __restrict__ Ch, __nv_bfloat16* __restrict__ Cl,
    int M, int N, int K)
{
    extern __shared__ char smem[];
    const uint32_t sbase = smem_u32(smem);

    const int tid  = threadIdx.x;
    const int wid  = tid >> 5;
    const int lane = tid & 31;
    const int wm   = wid & 1;
    const int wn   = wid >> 1;
    const int lr   = lane >> 2;
    const int lc   = lane & 3;

    const int m0 = blockIdx.y * 128;
    const int n0 = blockIdx.x * 128;

    const int lrow0 = tid >> 2;
    const int lcc0  = tid & 3;

    const size_t aBase = (size_t)m0 * K;
    const size_t bBase = (size_t)n0 * K;

    auto load_tile = [&](int buf, int kt) {
        uint32_t sb = sbase + buf * BUF_B;
        const size_t gk = (size_t)kt * 32;
#pragma unroll
        for (int j = 0; j < 2; ++j) {
            int row = lrow0 + j * 64;
            uint32_t soff = (uint32_t)(row * PITCH_B + lcc0 * 16);
            size_t   goff = aBase + (size_t)row * K + gk + lcc0 * 8;
            cpasync16(sb + OFF_AHI + soff, Ah + goff);
            cpasync16(sb + OFF_ALO + soff, Al + goff);
            size_t   goffb = bBase + (size_t)row * K + gk + lcc0 * 8;
            cpasync16(sb + OFF_BHI + soff, Bh + goffb);
            cpasync16(sb + OFF_BLO + soff, Bl + goffb);
        }
        CP_COMMIT();
    };

    float acc[4][4][4];
#pragma unroll
    for (int i = 0; i < 4; ++i)
#pragma unroll
        for (int j = 0; j < 4; ++j)
#pragma unroll
            for (int r = 0; r < 4; ++r) acc[i][j][r] = 0.f;

    const uint32_t aRB = (uint32_t)((wm * 64 + lr) * PITCH_B + lc * 4);
    const uint32_t bRB = (uint32_t)((wn * 32 + lr) * PITCH_B + lc * 4);

    load_tile(0, 0);

    const int nk = K >> 5;
    for (int kt = 0; kt < nk; ++kt) {
        const int cur = kt & 1;
        if (kt + 1 < nk) { load_tile(cur ^ 1, kt + 1); CP_WAIT(1); }
        else             { CP_WAIT(0); }
        __syncthreads();

        const char* Sa_h = smem + cur * BUF_B + OFF_AHI;
        const char* Sa_l = smem + cur * BUF_B + OFF_ALO;
        const char* Sb_h = smem + cur * BUF_B + OFF_BHI;
        const char* Sb_l = smem + cur * BUF_B + OFF_BLO;

#pragma unroll
        for (int ks = 0; ks < 2; ++ks) {
            const uint32_t ko = (uint32_t)(ks * 32);

            uint32_t ahi[4][4];
#pragma unroll
            for (int mi = 0; mi < 4; ++mi) {
                uint32_t o = aRB + mi * (16 * PITCH_B) + ko;
                ahi[mi][0] = *(const uint32_t*)(Sa_h + o);
                ahi[mi][1] = *(const uint32_t*)(Sa_h + o + 8 * PITCH_B);
                ahi[mi][2] = *(const uint32_t*)(Sa_h + o + 16);
                ahi[mi][3] = *(const uint32_t*)(Sa_h + o + 8 * PITCH_B + 16);
            }
            uint32_t bhi[4][2];
#pragma unroll
            for (int ni = 0; ni < 4; ++ni) {
                uint32_t o = bRB + ni * (8 * PITCH_B) + ko;
                bhi[ni][0] = *(const uint32_t*)(Sb_h + o);
                bhi[ni][1] = *(const uint32_t*)(Sb_h + o + 16);
            }
#pragma unroll
            for (int mi = 0; mi < 4; ++mi)
#pragma unroll
                for (int ni = 0; ni < 4; ++ni)
                    mma16816(acc[mi][ni], ahi[mi], bhi[ni][0], bhi[ni][1]);

            uint32_t blo[4][2];
#pragma unroll
            for (int ni = 0; ni < 4; ++ni) {
                uint32_t o = bRB + ni * (8 * PITCH_B) + ko;
                blo[ni][0] = *(const uint32_t*)(Sb_l + o);
                blo[ni][1] = *(const uint32_t*)(Sb_l + o + 16);
            }
#pragma unroll
            for (int mi = 0; mi < 4; ++mi)
#pragma unroll
                for (int ni = 0; ni < 4; ++ni)
                    mma16816(acc[mi][ni], ahi[mi], blo[ni][0], blo[ni][1]);

            uint32_t alo[4][4];
#pragma unroll
            for (int mi = 0; mi < 4; ++mi) {
                uint32_t o = aRB + mi * (16 * PITCH_B) + ko;
                alo[mi][0] = *(const uint32_t*)(Sa_l + o);
                alo[mi][1] = *(const uint32_t*)(Sa_l + o + 8 * PITCH_B);
                alo[mi][2] = *(const uint32_t*)(Sa_l + o + 16);
                alo[mi][3] = *(const uint32_t*)(Sa_l + o + 8 * PITCH_B + 16);
            }
#pragma unroll
            for (int mi = 0; mi < 4; ++mi)
#pragma unroll
                for (int ni = 0; ni < 4; ++ni)
                    mma16816(acc[mi][ni], alo[mi], bhi[ni][0], bhi[ni][1]);
        }
        __syncthreads();
    }

#pragma unroll
    for (int mi = 0; mi < 4; ++mi) {
        int r = m0 + wm * 64 + mi * 16 + lr;
#pragma unroll
        for (int ni = 0; ni < 4; ++ni) {
            int c = n0 + wn * 32 + ni * 8 + lc * 2;
            float b0 = __ldg(bias + c), b1 = __ldg(bias + c + 1);
            float v00 = acc[mi][ni][0] + b0, v01 = acc[mi][ni][1] + b1;
            float v10 = acc[mi][ni][2] + b0, v11 = acc[mi][ni][3] + b1;
            if (SPLIT) {
                uint32_t h, l;
                split2(v00, v01, h, l);
                *(uint32_t*)&Ch[(size_t)r * N + c] = h;
                *(uint32_t*)&Cl[(size_t)r * N + c] = l;
                split2(v10, v11, h, l);
                *(uint32_t*)&Ch[(size_t)(r + 8) * N + c] = h;
                *(uint32_t*)&Cl[(size_t)(r + 8) * N + c] = l;
            } else {
                *(float2*)&C[(size_t)r * N + c]       = make_float2(v00, v01);
                *(float2*)&C[(size_t)(r + 8) * N + c] = make_float2(v10, v11);
            }
        }
    }
}

// ---------------------------------------------------------------------------
// Tensor-core flash attention (bf16x3 QK^T and PV, fp32 softmax).
// Block = (b,h) x 128 q-rows. 8 warps, each owns 16 q-rows.
// KV streamed in 64-row chunks, cp.async double-buffered, SW128 128B rows.
// ---------------------------------------------------------------------------
#define FSM_QH   0
#define FSM_QL   16384
#define FSM_ST   32768
#define ST_KH    0
#define ST_KL    8192
#define ST_VH    16384
#define ST_VL    24576
#define ST_SZ    32768
#define FLASH_SMEM (FSM_ST + 2 * ST_SZ)   // 98304 B

__global__ __launch_bounds__(256) void flash_mma()
{
    extern __shared__ char sm[];
    const uint32_t sb = smem_u32(sm);

    const int tid  = threadIdx.x;
    const int wid  = tid >> 5;
    const int lane = tid & 31;
    const int b    = blockIdx.y >> 4;
    const int h    = blockIdx.y & 15;
    const int q0   = blockIdx.x * 128;

    // ---- load Q tile (128 x 64 bf16 hi/lo) into smem ----
    {
        const size_t qtok = (size_t)(b * SQL + q0);
#pragma unroll
        for (int i = 0; i < 4; ++i) {
            int idx = i * 256 + tid;
            int r = idx >> 3, cc = idx & 7;
            uint32_t off = SWZ(r * 128 + cc * 16);
            size_t g = (qtok + r) * EMBED + h * 64 + cc * 8;
            cpasync16(sb + FSM_QH + off, g_Qh + g);
            cpasync16(sb + FSM_QL + off, g_Ql + g);
        }
    }
    // ---- KV chunk loader ----
    auto load_kv = [&](int buf, int kb) {
        uint32_t st = sb + FSM_ST + buf * ST_SZ;
        const size_t tok = (size_t)(b * SKVL + kb * 64);
#pragma unroll
        for (int i = 0; i < 2; ++i) {
            int idx = i * 256 + tid;
            int r = idx >> 3, cc = idx & 7;
            uint32_t off = SWZ(r * 128 + cc * 16);
            size_t g = (tok + r) * EMBED + h * 64 + cc * 8;
            cpasync16(st + ST_KH + off, g_Kh + g);
            cpasync16(st + ST_KL + off, g_Kl + g);
            cpasync16(st + ST_VH + off, g_Vh + g);
            cpasync16(st + ST_VL + off, g_Vl + g);
        }
    };
    load_kv(0, 0);
    CP_COMMIT();   // group: Q + stage0

    float m_[2] = {-1e30f, -1e30f};
    float l_[2] = {0.f, 0.f};
    float o[8][4];
#pragma unroll
    for (int i = 0; i < 8; ++i)
#pragma unroll
        for (int j = 0; j < 4; ++j) o[i][j] = 0.f;

    // ldmatrix lane addressing: row = base + (lane&15), 16B-chunk = base + (lane>>4)
    const int lrow = lane & 15;
    const int lchk = lane >> 4;
    const float scale = 0.125f;

    const int NCH = SKVL / 64;
    for (int ch = 0; ch < NCH; ++ch) {
        const int cur = ch & 1;
        if (ch + 1 < NCH) { load_kv(cur ^ 1, ch + 1); CP_COMMIT(); CP_WAIT(1); }
        else              { CP_WAIT(0); }
        __syncthreads();

        const uint32_t st = sb + FSM_ST + cur * ST_SZ;

        // ---- S = Q K^T (raw, scaled later) ----
        float s[8][4];
#pragma unroll
        for (int i = 0; i < 8; ++i)
#pragma unroll
            for (int j = 0; j < 4; ++j) s[i][j] = 0.f;

#pragma unroll
        for (int kk = 0; kk < 4; ++kk) {
            uint32_t qoff = SWZ((wid * 16 + lrow) * 128 + (kk * 2 + lchk) * 16);
            uint32_t qh[4], ql[4];
            ldsm_x4(qh, sb + FSM_QH + qoff);
            ldsm_x4(ql, sb + FSM_QL + qoff);
#pragma unroll
            for (int cg = 0; cg < 4; ++cg) {
                uint32_t koff = SWZ((cg * 16 + lrow) * 128 + (kk * 2 + lchk) * 16);
                uint32_t kh[4], kl[4];
                ldsm_x4(kh, st + ST_KH + koff);
                ldsm_x4(kl, st + ST_KL + koff);
                mma16816(s[2 * cg],     qh, kh[0], kh[2]);
                mma16816(s[2 * cg],     qh, kl[0], kl[2]);
                mma16816(s[2 * cg],     ql, kh[0], kh[2]);
                mma16816(s[2 * cg + 1], qh, kh[1], kh[3]);
                mma16816(s[2 * cg + 1], qh, kl[1], kl[3]);
                mma16816(s[2 * cg + 1], ql, kh[1], kh[3]);
            }
        }

        // ---- online softmax (rows lr and lr+8; reduce over 4 lanes sharing lr) ----
        float rm0 = -1e30f, rm1 = -1e30f;
#pragma unroll
        for (int ni = 0; ni < 8; ++ni) {
            rm0 = fmaxf(rm0, fmaxf(s[ni][0], s[ni][1]));
            rm1 = fmaxf(rm1, fmaxf(s[ni][2], s[ni][3]));
        }
        rm0 = fmaxf(rm0, __shfl_xor_sync(0xffffffffu, rm0, 1));
        rm0 = fmaxf(rm0, __shfl_xor_sync(0xffffffffu, rm0, 2));
        rm1 = fmaxf(rm1, __shfl_xor_sync(0xffffffffu, rm1, 1));
        rm1 = fmaxf(rm1, __shfl_xor_sync(0xffffffffu, rm1, 2));

        float mn0 = fmaxf(m_[0], rm0 * scale);
        float mn1 = fmaxf(m_[1], rm1 * scale);
        float a0 = __expf(m_[0] - mn0);
        float a1 = __expf(m_[1] - mn1);
        m_[0] = mn0; m_[1] = mn1;
#pragma unroll
        for (int nd = 0; nd < 8; ++nd) {
            o[nd][0] *= a0; o[nd][1] *= a0;
            o[nd][2] *= a1; o[nd][3] *= a1;
        }
        float rs0 = 0.f, rs1 = 0.f;
#pragma unroll
        for (int ni = 0; ni < 8; ++ni) {
            s[ni][0] = __expf(fmaf(s[ni][0], scale, -mn0));
            s[ni][1] = __expf(fmaf(s[ni][1], scale, -mn0));
            s[ni][2] = __expf(fmaf(s[ni][2], scale, -mn1));
            s[ni][3] = __expf(fmaf(s[ni][3], scale, -mn1));
            rs0 += s[ni][0] + s[ni][1];
            rs1 += s[ni][2] + s[ni][3];
        }
        rs0 += __shfl_xor_sync(0xffffffffu, rs0, 1);
        rs0 += __shfl_xor_sync(0xffffffffu, rs0, 2);
        rs1 += __shfl_xor_sync(0xffffffffu, rs1, 1);
        rs1 += __shfl_xor_sync(0xffffffffu, rs1, 2);
        l_[0] = l_[0] * a0 + rs0;
        l_[1] = l_[1] * a1 + rs1;

        // ---- O += P V (P repacked from accumulators, V via ldmatrix.trans) ----
#pragma unroll
        for (int kc = 0; kc < 4; ++kc) {
            uint32_t ph[4], pl[4];
            split2(s[2 * kc][0],     s[2 * kc][1],     ph[0], pl[0]);
            split2(s[2 * kc][2],     s[2 * kc][3],     ph[1], pl[1]);
            split2(s[2 * kc + 1][0], s[2 * kc + 1][1], ph[2], pl[2]);
            split2(s[2 * kc + 1][2], s[2 * kc + 1][3], ph[3], pl[3]);
#pragma unroll
            for (int g = 0; g < 4; ++g) {
                uint32_t voff = SWZ((kc * 16 + lrow) * 128 + (g * 2 + lchk) * 16);
                uint32_t vh[4], vl[4];
                ldsm_x4_t(vh, st + ST_VH + voff);
                ldsm_x4_t(vl, st + ST_VL + voff);
                mma16816(o[2 * g],     ph, vh[0], vh[1]);
                mma16816(o[2 * g],     ph, vl[0], vl[1]);
                mma16816(o[2 * g],     pl, vh[0], vh[1]);
                mma16816(o[2 * g + 1], ph, vh[2], vh[3]);
                mma16816(o[2 * g + 1], ph, vl[2], vl[3]);
                mma16816(o[2 * g + 1], pl, vh[2], vh[3]);
            }
        }
        __syncthreads();   // all reads of buffer `cur` done before it is reloaded
    }

    // ---- epilogue: normalize, split to bf16 hi/lo, store ----
    const float inv0 = 1.f / l_[0];
    const float inv1 = 1.f / l_[1];
    const int r0 = q0 + wid * 16 + (lane >> 2);
    const int cb = h * 64 + (lane & 3) * 2;
    const size_t tok = (size_t)b * SQL;
#pragma unroll
    for (int nd = 0; nd < 8; ++nd) {
        int c = cb + nd * 8;
        uint32_t hh, ll;
        split2(o[nd][0] * inv0, o[nd][1] * inv0, hh, ll);
        *(uint32_t*)&g_aoh[(tok + r0) * EMBED + c] = hh;
        *(uint32_t*)&g_aol[(tok + r0) * EMBED + c] = ll;
        split2(o[nd][2] * inv1, o[nd][3] * inv1, hh, ll);
        *(uint32_t*)&g_aoh[(tok + r0 + 8) * EMBED + c] = hh;
        *(uint32_t*)&g_aol[(tok + r0 + 8) * EMBED + c] = ll;
    }
}

// ---------------------------------------------------------------------------
// Launch
// ---------------------------------------------------------------------------
extern "C" void kernel_launch(void* const* d_in, const int* in_sizes, int n_in,
                              void* d_out, int out_size)
{
    const float* x   = (const float*)d_in[0];
    const float* ctx = (const float*)d_in[1];
    const float* Wq  = (const float*)d_in[2];
    const float* bq  = (const float*)d_in[3];
    const float* Wk  = (const float*)d_in[4];
    const float* bk  = (const float*)d_in[5];
    const float* Wv  = (const float*)d_in[6];
    const float* bv  = (const float*)d_in[7];
    const float* Wp  = (const float*)d_in[8];
    const float* bp  = (const float*)d_in[9];
    float* out = (float*)d_out;

    __nv_bfloat16 *Qh, *Ql, *Kh, *Kl, *Vh, *Vl, *xh, *xl, *ch_, *cl_, *aoh, *aol;
    __nv_bfloat16 *WqTh, *WqTl, *WkTh, *WkTl, *WvTh, *WvTl, *WpTh, *WpTl;
    cudaGetSymbolAddress((void**)&Qh,  g_Qh);
    cudaGetSymbolAddress((void**)&Ql,  g_Ql);
    cudaGetSymbolAddress((void**)&Kh,  g_Kh);
    cudaGetSymbolAddress((void**)&Kl,  g_Kl);
    cudaGetSymbolAddress((void**)&Vh,  g_Vh);
    cudaGetSymbolAddress((void**)&Vl,  g_Vl);
    cudaGetSymbolAddress((void**)&xh,  g_xh);
    cudaGetSymbolAddress((void**)&xl,  g_xl);
    cudaGetSymbolAddress((void**)&ch_, g_ch);
    cudaGetSymbolAddress((void**)&cl_, g_cl);
    cudaGetSymbolAddress((void**)&aoh, g_aoh);
    cudaGetSymbolAddress((void**)&aol, g_aol);
    cudaGetSymbolAddress((void**)&WqTh, g_WqTh);
    cudaGetSymbolAddress((void**)&WqTl, g_WqTl);
    cudaGetSymbolAddress((void**)&WkTh, g_WkTh);
    cudaGetSymbolAddress((void**)&WkTl, g_WkTl);
    cudaGetSymbolAddress((void**)&WvTh, g_WvTh);
    cudaGetSymbolAddress((void**)&WvTl, g_WvTl);
    cudaGetSymbolAddress((void**)&WpTh, g_WpTh);
    cudaGetSymbolAddress((void**)&WpTl, g_WpTl);

    cudaFuncSetAttribute(gemm_bf16x3<false>,
                         cudaFuncAttributeMaxDynamicSharedMemorySize, GEMM_SMEM);
    cudaFuncSetAttribute(gemm_bf16x3<true>,
                         cudaFuncAttributeMaxDynamicSharedMemorySize, GEMM_SMEM);
    cudaFuncSetAttribute(flash_mma,
                         cudaFuncAttributeMaxDynamicSharedMemorySize, FLASH_SMEM);

    const int NX = BATCH * SQL  * EMBED;
    const int NC = BATCH * SKVL * EMBED;

    // Split inputs + weights
    split_f32<<<(NX / 4 + 255) / 256, 256>>>((const float4*)x,   xh,  xl,  NX / 4);
    split_f32<<<(NC / 4 + 255) / 256, 256>>>((const float4*)ctx, ch_, cl_, NC / 4);
    transpose_split<<<dim3(EMBED / 32, EMBED / 32), dim3(32, 8)>>>(Wq, WqTh, WqTl, EMBED, EMBED);
    transpose_split<<<dim3(EMBED / 32, EMBED / 32), dim3(32, 8)>>>(Wk, WkTh, WkTl, EMBED, EMBED);
    transpose_split<<<dim3(EMBED / 32, EMBED / 32), dim3(32, 8)>>>(Wv, WvTh, WvTl, EMBED, EMBED);
    transpose_split<<<dim3(VOCAB / 32, EMBED / 32), dim3(32, 8)>>>(Wp, WpTh, WpTl, EMBED, VOCAB);

    // Projections -> pre-split bf16 hi/lo Q/K/V
    gemm_bf16x3<true><<<dim3(EMBED / 128, (BATCH * SQL) / 128), 256, GEMM_SMEM>>>(
        xh, xl, WqTh, WqTl, bq, nullptr, Qh, Ql, BATCH * SQL, EMBED, EMBED);
    gemm_bf16x3<true><<<dim3(EMBED / 128, (BATCH * SKVL) / 128), 256, GEMM_SMEM>>>(
        ch_, cl_, WkTh, WkTl, bk, nullptr, Kh, Kl, BATCH * SKVL, EMBED, EMBED);
    gemm_bf16x3<true><<<dim3(EMBED / 128, (BATCH * SKVL) / 128), 256, GEMM_SMEM>>>(
        ch_, cl_, WvTh, WvTl, bv, nullptr, Vh, Vl, BATCH * SKVL, EMBED, EMBED);

    // Tensor-core flash attention -> pre-split AO hi/lo
    flash_mma<<<dim3(SQL / 128, BATCH * NHEADS), 256, FLASH_SMEM>>>();

    // Output projection
    gemm_bf16x3<false><<<dim3(VOCAB / 128, (BATCH * SQL) / 128), 256, GEMM_SMEM>>>(
        aoh, aol, WpTh, WpTl, bp, out, nullptr, nullptr, BATCH * SQL, VOCAB, EMBED);
}

// round 8
// speedup vs baseline: 2.2789x; 1.0106x over previous
#include <cuda_runtime.h>
#include <cuda_bf16.h>
#include <math.h>
#include <stdint.h>

#define EMBED  1024
#define NHEADS 16
#define HDIM   64
#define VOCAB  4096
#define BATCH  2
#define SQL    1024
#define SKVL   2048

// ---------------------------------------------------------------------------
// Scratch (allocation-free __device__ globals)
// ---------------------------------------------------------------------------
__device__ __align__(16) __nv_bfloat16 g_Qh [BATCH * SQL  * EMBED];
__device__ __align__(16) __nv_bfloat16 g_Ql [BATCH * SQL  * EMBED];
__device__ __align__(16) __nv_bfloat16 g_Kh [BATCH * SKVL * EMBED];
__device__ __align__(16) __nv_bfloat16 g_Kl [BATCH * SKVL * EMBED];
__device__ __align__(16) __nv_bfloat16 g_Vh [BATCH * SKVL * EMBED];
__device__ __align__(16) __nv_bfloat16 g_Vl [BATCH * SKVL * EMBED];
__device__ __align__(16) __nv_bfloat16 g_xh [BATCH * SQL  * EMBED];
__device__ __align__(16) __nv_bfloat16 g_xl [BATCH * SQL  * EMBED];
__device__ __align__(16) __nv_bfloat16 g_ch [BATCH * SKVL * EMBED];
__device__ __align__(16) __nv_bfloat16 g_cl [BATCH * SKVL * EMBED];
__device__ __align__(16) __nv_bfloat16 g_aoh[BATCH * SQL  * EMBED];
__device__ __align__(16) __nv_bfloat16 g_aol[BATCH * SQL  * EMBED];
__device__ __align__(16) __nv_bfloat16 g_WqTh[EMBED * EMBED];
__device__ __align__(16) __nv_bfloat16 g_WqTl[EMBED * EMBED];
__device__ __align__(16) __nv_bfloat16 g_WkTh[EMBED * EMBED];
__device__ __align__(16) __nv_bfloat16 g_WkTl[EMBED * EMBED];
__device__ __align__(16) __nv_bfloat16 g_WvTh[EMBED * EMBED];
__device__ __align__(16) __nv_bfloat16 g_WvTl[EMBED * EMBED];
__device__ __align__(16) __nv_bfloat16 g_WpTh[VOCAB * EMBED];
__device__ __align__(16) __nv_bfloat16 g_WpTl[VOCAB * EMBED];

// ---------------------------------------------------------------------------
// Helpers
// ---------------------------------------------------------------------------
__device__ __forceinline__ uint32_t smem_u32(const void* p) {
    uint32_t a;
    asm("{ .reg .u64 t; cvta.to.shared.u64 t, %1; cvt.u32.u64 %0, t; }"
        : "=r"(a) : "l"(p));
    return a;
}
__device__ __forceinline__ void cpasync16(uint32_t dst, const void* src) {
    asm volatile("cp.async.cg.shared.global [%0], [%1], 16;"
                 :: "r"(dst), "l"(src) : "memory");
}
#define CP_COMMIT() asm volatile("cp.async.commit_group;" ::: "memory")
#define CP_WAIT(N)  asm volatile("cp.async.wait_group %0;" :: "n"(N) : "memory")

__device__ __forceinline__ void mma16816(float* c, const uint32_t* a,
                                         uint32_t b0, uint32_t b1) {
    asm volatile(
        "mma.sync.aligned.m16n8k16.row.col.f32.bf16.bf16.f32 "
        "{%0,%1,%2,%3}, {%4,%5,%6,%7}, {%8,%9}, {%0,%1,%2,%3};"
        : "+f"(c[0]), "+f"(c[1]), "+f"(c[2]), "+f"(c[3])
        : "r"(a[0]), "r"(a[1]), "r"(a[2]), "r"(a[3]), "r"(b0), "r"(b1));
}
__device__ __forceinline__ void ldsm_x4(uint32_t* r, uint32_t addr) {
    asm volatile("ldmatrix.sync.aligned.m8n8.x4.shared.b16 {%0,%1,%2,%3}, [%4];"
                 : "=r"(r[0]), "=r"(r[1]), "=r"(r[2]), "=r"(r[3]) : "r"(addr));
}
__device__ __forceinline__ void ldsm_x4_t(uint32_t* r, uint32_t addr) {
    asm volatile("ldmatrix.sync.aligned.m8n8.x4.trans.shared.b16 {%0,%1,%2,%3}, [%4];"
                 : "=r"(r[0]), "=r"(r[1]), "=r"(r[2]), "=r"(r[3]) : "r"(addr));
}

__device__ __forceinline__ void split1(float v, __nv_bfloat16& h, __nv_bfloat16& l) {
    h = __float2bfloat16_rn(v);
    l = __float2bfloat16_rn(v - __bfloat162float(h));
}
__device__ __forceinline__ void split2(float a, float b, uint32_t& h, uint32_t& l) {
    __nv_bfloat162 hv = __floats2bfloat162_rn(a, b);
    __nv_bfloat162 lv = __floats2bfloat162_rn(a - __bfloat162float(hv.x),
                                              b - __bfloat162float(hv.y));
    h = *(uint32_t*)&hv;
    l = *(uint32_t*)&lv;
}

#define SWZ(off) ((uint32_t)(off) ^ ((((uint32_t)(off)) >> 3) & 0x70u))

// ---------------------------------------------------------------------------
// fp32 -> bf16 hi/lo split
// ---------------------------------------------------------------------------
__global__ __launch_bounds__(256) void split_f32(
    const float4* __restrict__ in,
    __nv_bfloat16* __restrict__ hi, __nv_bfloat16* __restrict__ lo, int n4)
{
    int i = blockIdx.x * 256 + threadIdx.x;
    if (i >= n4) return;
    float4 v = in[i];
    __nv_bfloat16 h[4], l[4];
    split1(v.x, h[0], l[0]); split1(v.y, h[1], l[1]);
    split1(v.z, h[2], l[2]); split1(v.w, h[3], l[3]);
    *(uint2*)&hi[i * 4] = *(uint2*)h;
    *(uint2*)&lo[i * 4] = *(uint2*)l;
}

// ---------------------------------------------------------------------------
// Weight transpose + split (z selects one of up to 3 weight sets)
// ---------------------------------------------------------------------------
struct TSet { const float* W; __nv_bfloat16* Wh; __nv_bfloat16* Wl; };
struct TArgs { TSet s[3]; };

__device__ __forceinline__ void transpose_body(
    const float* __restrict__ W, __nv_bfloat16* __restrict__ WhT,
    __nv_bfloat16* __restrict__ WlT, int K, int N)
{
    __shared__ float t[32][33];
    int n  = blockIdx.x * 32 + threadIdx.x;
    int k0 = blockIdx.y * 32;
    for (int j = threadIdx.y; j < 32; j += 8)
        t[j][threadIdx.x] = W[(size_t)(k0 + j) * N + n];
    __syncthreads();
    int k  = blockIdx.y * 32 + threadIdx.x;
    int n0 = blockIdx.x * 32;
    for (int j = threadIdx.y; j < 32; j += 8) {
        float v = t[threadIdx.x][j];
        __nv_bfloat16 h, l;
        split1(v, h, l);
        WhT[(size_t)(n0 + j) * K + k] = h;
        WlT[(size_t)(n0 + j) * K + k] = l;
    }
}
__global__ void transpose_split3(TArgs a, int K, int N) {
    const TSet& s = a.s[blockIdx.z];
    transpose_body(s.W, s.Wh, s.Wl, K, N);
}
__global__ void transpose_split(const float* __restrict__ W,
                                __nv_bfloat16* __restrict__ WhT,
                                __nv_bfloat16* __restrict__ WlT, int K, int N) {
    transpose_body(W, WhT, WlT, K, N);
}

// ---------------------------------------------------------------------------
// bf16x3 GEMM core: C = Ah/Al @ (Bh/Bl)^T + bias.
// CTA 128x128, k-tile 32, 256 threads, warp tile 64x32, cp.async double-buffer,
// ldmatrix.x4 fragment feeding (flash-proven addressing), 80B pitch.
// ---------------------------------------------------------------------------
#define PITCH_B   80
#define TILE_B    (128 * PITCH_B)
#define OFF_AHI   0
#define OFF_ALO   (TILE_B)
#define OFF_BHI   (2 * TILE_B)
#define OFF_BLO   (3 * TILE_B)
#define BUF_B     (4 * TILE_B)
#define GEMM_SMEM (2 * BUF_B)

template<bool SPLIT>
__device__ __forceinline__ void gemm_core(
    const __nv_bfloat16* __restrict__ Ah, const __nv_bfloat16* __restrict__ Al,
    const __nv_bfloat16* __restrict__ Bh, const __nv_bfloat16* __restrict__ Bl,
    const float* __restrict__ bias, float* __restrict__ C,
    __nv_bfloat16* __restrict__ Ch, __nv_bfloat16* __restrict__ Cl,
    int N, int K, char* smem)
{
    const uint32_t sbase = smem_u32(smem);

    const int tid  = threadIdx.x;
    const int wid  = tid >> 5;
    const int lane = tid & 31;
    const int wm   = wid & 1;
    const int wn   = wid >> 1;
    const int lr   = lane >> 2;
    const int lc   = lane & 3;

    const int m0 = blockIdx.y * 128;
    const int n0 = blockIdx.x * 128;

    const int lrow0 = tid >> 2;
    const int lcc0  = tid & 3;

    const size_t aBase = (size_t)m0 * K;
    const size_t bBase = (size_t)n0 * K;

    auto load_tile = [&](int buf, int kt) {
        uint32_t sb = sbase + buf * BUF_B;
        const size_t gk = (size_t)kt * 32;
#pragma unroll
        for (int j = 0; j < 2; ++j) {
            int row = lrow0 + j * 64;
            uint32_t soff = (uint32_t)(row * PITCH_B + lcc0 * 16);
            size_t   goff = aBase + (size_t)row * K + gk + lcc0 * 8;
            cpasync16(sb + OFF_AHI + soff, Ah + goff);
            cpasync16(sb + OFF_ALO + soff, Al + goff);
            size_t   goffb = bBase + (size_t)row * K + gk + lcc0 * 8;
            cpasync16(sb + OFF_BHI + soff, Bh + goffb);
            cpasync16(sb + OFF_BLO + soff, Bl + goffb);
        }
        CP_COMMIT();
    };

    float acc[4][4][4];
#pragma unroll
    for (int i = 0; i < 4; ++i)
#pragma unroll
        for (int j = 0; j < 4; ++j)
#pragma unroll
            for (int r = 0; r < 4; ++r) acc[i][j][r] = 0.f;

    // ldmatrix per-thread base offsets (row = lane&15, chunk = lane>>4)
    const uint32_t aOff = (uint32_t)((wm * 64 + (lane & 15)) * PITCH_B
                                     + (lane >> 4) * 16);
    const uint32_t bOff = (uint32_t)((wn * 32 + (lane & 15)) * PITCH_B
                                     + (lane >> 4) * 16);

    load_tile(0, 0);

    const int nk = K >> 5;
    for (int kt = 0; kt < nk; ++kt) {
        const int cur = kt & 1;
        if (kt + 1 < nk) { load_tile(cur ^ 1, kt + 1); CP_WAIT(1); }
        else             { CP_WAIT(0); }
        __syncthreads();

        const uint32_t sA_h = sbase + cur * BUF_B + OFF_AHI;
        const uint32_t sA_l = sbase + cur * BUF_B + OFF_ALO;
        const uint32_t sB_h = sbase + cur * BUF_B + OFF_BHI;
        const uint32_t sB_l = sbase + cur * BUF_B + OFF_BLO;

#pragma unroll
        for (int ks = 0; ks < 2; ++ks) {
            const uint32_t ko = (uint32_t)(ks * 32);

            uint32_t ah[4][4];
#pragma unroll
            for (int mi = 0; mi < 4; ++mi)
                ldsm_x4(ah[mi], sA_h + aOff + mi * (16 * PITCH_B) + ko);
            uint32_t bh[2][4];
#pragma unroll
            for (int g = 0; g < 2; ++g)
                ldsm_x4(bh[g], sB_h + bOff + g * (16 * PITCH_B) + ko);
#pragma unroll
            for (int mi = 0; mi < 4; ++mi)
#pragma unroll
                for (int ni = 0; ni < 4; ++ni)
                    mma16816(acc[mi][ni], ah[mi],
                             bh[ni >> 1][ni & 1], bh[ni >> 1][(ni & 1) + 2]);

            uint32_t bl[2][4];
#pragma unroll
            for (int g = 0; g < 2; ++g)
                ldsm_x4(bl[g], sB_l + bOff + g * (16 * PITCH_B) + ko);
#pragma unroll
            for (int mi = 0; mi < 4; ++mi)
#pragma unroll
                for (int ni = 0; ni < 4; ++ni)
                    mma16816(acc[mi][ni], ah[mi],
                             bl[ni >> 1][ni & 1], bl[ni >> 1][(ni & 1) + 2]);

#pragma unroll
            for (int mi = 0; mi < 4; ++mi) {
                uint32_t al[4];
                ldsm_x4(al, sA_l + aOff + mi * (16 * PITCH_B) + ko);
#pragma unroll
                for (int ni = 0; ni < 4; ++ni)
                    mma16816(acc[mi][ni], al,
                             bh[ni >> 1][ni & 1], bh[ni >> 1][(ni & 1) + 2]);
            }
        }
        __syncthreads();
    }

#pragma unroll
    for (int mi = 0; mi < 4; ++mi) {
        int r = m0 + wm * 64 + mi * 16 + lr;
#pragma unroll
        for (int ni = 0; ni < 4; ++ni) {
            int c = n0 + wn * 32 + ni * 8 + lc * 2;
            float b0 = __ldg(bias + c), b1 = __ldg(bias + c + 1);
            float v00 = acc[mi][ni][0] + b0, v01 = acc[mi][ni][1] + b1;
            float v10 = acc[mi][ni][2] + b0, v11 = acc[mi][ni][3] + b1;
            if (SPLIT) {
                uint32_t h, l;
                split2(v00, v01, h, l);
                *(uint32_t*)&Ch[(size_t)r * N + c] = h;
                *(uint32_t*)&Cl[(size_t)r * N + c] = l;
                split2(v10, v11, h, l);
                *(uint32_t*)&Ch[(size_t)(r + 8) * N + c] = h;
                *(uint32_t*)&Cl[(size_t)(r + 8) * N + c] = l;
            } else {
                *(float2*)&C[(size_t)r * N + c]       = make_float2(v00, v01);
                *(float2*)&C[(size_t)(r + 8) * N + c] = make_float2(v10, v11);
            }
        }
    }
}

// Output projection (fp32 out)
__global__ __launch_bounds__(256, 2) void gemm_out(
    const __nv_bfloat16* __restrict__ Ah, const __nv_bfloat16* __restrict__ Al,
    const __nv_bfloat16* __restrict__ Bh, const __nv_bfloat16* __restrict__ Bl,
    const float* __restrict__ bias, float* __restrict__ C, int N, int K)
{
    extern __shared__ char smem[];
    gemm_core<false>(Ah, Al, Bh, Bl, bias, C, nullptr, nullptr, N, K, smem);
}

// Fused Q/K/V projections: blockIdx.z selects the operand set; z==0 (Q) has
// half the rows (blockIdx.y >= 16 exits before any __syncthreads).
struct GSet {
    const __nv_bfloat16 *Ah, *Al, *Bh, *Bl;
    const float* bias;
    __nv_bfloat16 *Ch, *Cl;
};
struct QKVArgs { GSet s[3]; };

__global__ __launch_bounds__(256, 2) void gemm_qkv(QKVArgs a)
{
    extern __shared__ char smem[];
    if (blockIdx.z == 0 && blockIdx.y >= (BATCH * SQL) / 128) return;
    const GSet& s = a.s[blockIdx.z];
    gemm_core<true>(s.Ah, s.Al, s.Bh, s.Bl, s.bias, nullptr, s.Ch, s.Cl,
                    EMBED, EMBED, smem);
}

// ---------------------------------------------------------------------------
// Tensor-core flash attention (UNCHANGED from passing round-6 kernel)
// ---------------------------------------------------------------------------
#define FSM_QH   0
#define FSM_QL   16384
#define FSM_ST   32768
#define ST_KH    0
#define ST_KL    8192
#define ST_VH    16384
#define ST_VL    24576
#define ST_SZ    32768
#define FLASH_SMEM (FSM_ST + 2 * ST_SZ)   // 98304 B

__global__ __launch_bounds__(256) void flash_mma()
{
    extern __shared__ char sm[];
    const uint32_t sb = smem_u32(sm);

    const int tid  = threadIdx.x;
    const int wid  = tid >> 5;
    const int lane = tid & 31;
    const int b    = blockIdx.y >> 4;
    const int h    = blockIdx.y & 15;
    const int q0   = blockIdx.x * 128;

    {
        const size_t qtok = (size_t)(b * SQL + q0);
#pragma unroll
        for (int i = 0; i < 4; ++i) {
            int idx = i * 256 + tid;
            int r = idx >> 3, cc = idx & 7;
            uint32_t off = SWZ(r * 128 + cc * 16);
            size_t g = (qtok + r) * EMBED + h * 64 + cc * 8;
            cpasync16(sb + FSM_QH + off, g_Qh + g);
            cpasync16(sb + FSM_QL + off, g_Ql + g);
        }
    }
    auto load_kv = [&](int buf, int kb) {
        uint32_t st = sb + FSM_ST + buf * ST_SZ;
        const size_t tok = (size_t)(b * SKVL + kb * 64);
#pragma unroll
        for (int i = 0; i < 2; ++i) {
            int idx = i * 256 + tid;
            int r = idx >> 3, cc = idx & 7;
            uint32_t off = SWZ(r * 128 + cc * 16);
            size_t g = (tok + r) * EMBED + h * 64 + cc * 8;
            cpasync16(st + ST_KH + off, g_Kh + g);
            cpasync16(st + ST_KL + off, g_Kl + g);
            cpasync16(st + ST_VH + off, g_Vh + g);
            cpasync16(st + ST_VL + off, g_Vl + g);
        }
    };
    load_kv(0, 0);
    CP_COMMIT();

    float m_[2] = {-1e30f, -1e30f};
    float l_[2] = {0.f, 0.f};
    float o[8][4];
#pragma unroll
    for (int i = 0; i < 8; ++i)
#pragma unroll
        for (int j = 0; j < 4; ++j) o[i][j] = 0.f;

    const int lrow = lane & 15;
    const int lchk = lane >> 4;
    const float scale = 0.125f;

    const int NCH = SKVL / 64;
    for (int ch = 0; ch < NCH; ++ch) {
        const int cur = ch & 1;
        if (ch + 1 < NCH) { load_kv(cur ^ 1, ch + 1); CP_COMMIT(); CP_WAIT(1); }
        else              { CP_WAIT(0); }
        __syncthreads();

        const uint32_t st = sb + FSM_ST + cur * ST_SZ;

        float s[8][4];
#pragma unroll
        for (int i = 0; i < 8; ++i)
#pragma unroll
            for (int j = 0; j < 4; ++j) s[i][j] = 0.f;

#pragma unroll
        for (int kk = 0; kk < 4; ++kk) {
            uint32_t qoff = SWZ((wid * 16 + lrow) * 128 + (kk * 2 + lchk) * 16);
            uint32_t qh[4], ql[4];
            ldsm_x4(qh, sb + FSM_QH + qoff);
            ldsm_x4(ql, sb + FSM_QL + qoff);
#pragma unroll
            for (int cg = 0; cg < 4; ++cg) {
                uint32_t koff = SWZ((cg * 16 + lrow) * 128 + (kk * 2 + lchk) * 16);
                uint32_t kh[4], kl[4];
                ldsm_x4(kh, st + ST_KH + koff);
                ldsm_x4(kl, st + ST_KL + koff);
                mma16816(s[2 * cg],     qh, kh[0], kh[2]);
                mma16816(s[2 * cg],     qh, kl[0], kl[2]);
                mma16816(s[2 * cg],     ql, kh[0], kh[2]);
                mma16816(s[2 * cg + 1], qh, kh[1], kh[3]);
                mma16816(s[2 * cg + 1], qh, kl[1], kl[3]);
                mma16816(s[2 * cg + 1], ql, kh[1], kh[3]);
            }
        }

        float rm0 = -1e30f, rm1 = -1e30f;
#pragma unroll
        for (int ni = 0; ni < 8; ++ni) {
            rm0 = fmaxf(rm0, fmaxf(s[ni][0], s[ni][1]));
            rm1 = fmaxf(rm1, fmaxf(s[ni][2], s[ni][3]));
        }
        rm0 = fmaxf(rm0, __shfl_xor_sync(0xffffffffu, rm0, 1));
        rm0 = fmaxf(rm0, __shfl_xor_sync(0xffffffffu, rm0, 2));
        rm1 = fmaxf(rm1, __shfl_xor_sync(0xffffffffu, rm1, 1));
        rm1 = fmaxf(rm1, __shfl_xor_sync(0xffffffffu, rm1, 2));

        float mn0 = fmaxf(m_[0], rm0 * scale);
        float mn1 = fmaxf(m_[1], rm1 * scale);
        float a0 = __expf(m_[0] - mn0);
        float a1 = __expf(m_[1] - mn1);
        m_[0] = mn0; m_[1] = mn1;
#pragma unroll
        for (int nd = 0; nd < 8; ++nd) {
            o[nd][0] *= a0; o[nd][1] *= a0;
            o[nd][2] *= a1; o[nd][3] *= a1;
        }
        float rs0 = 0.f, rs1 = 0.f;
#pragma unroll
        for (int ni = 0; ni < 8; ++ni) {
            s[ni][0] = __expf(fmaf(s[ni][0], scale, -mn0));
            s[ni][1] = __expf(fmaf(s[ni][1], scale, -mn0));
            s[ni][2] = __expf(fmaf(s[ni][2], scale, -mn1));
            s[ni][3] = __expf(fmaf(s[ni][3], scale, -mn1));
            rs0 += s[ni][0] + s[ni][1];
            rs1 += s[ni][2] + s[ni][3];
        }
        rs0 += __shfl_xor_sync(0xffffffffu, rs0, 1);
        rs0 += __shfl_xor_sync(0xffffffffu, rs0, 2);
        rs1 += __shfl_xor_sync(0xffffffffu, rs1, 1);
        rs1 += __shfl_xor_sync(0xffffffffu, rs1, 2);
        l_[0] = l_[0] * a0 + rs0;
        l_[1] = l_[1] * a1 + rs1;

#pragma unroll
        for (int kc = 0; kc < 4; ++kc) {
            uint32_t ph[4], pl[4];
            split2(s[2 * kc][0],     s[2 * kc][1],     ph[0], pl[0]);
            split2(s[2 * kc][2],     s[2 * kc][3],     ph[1], pl[1]);
            split2(s[2 * kc + 1][0], s[2 * kc + 1][1], ph[2], pl[2]);
            split2(s[2 * kc + 1][2], s[2 * kc + 1][3], ph[3], pl[3]);
#pragma unroll
            for (int g = 0; g < 4; ++g) {
                uint32_t voff = SWZ((kc * 16 + lrow) * 128 + (g * 2 + lchk) * 16);
                uint32_t vh[4], vl[4];
                ldsm_x4_t(vh, st + ST_VH + voff);
                ldsm_x4_t(vl, st + ST_VL + voff);
                mma16816(o[2 * g],     ph, vh[0], vh[1]);
                mma16816(o[2 * g],     ph, vl[0], vl[1]);
                mma16816(o[2 * g],     pl, vh[0], vh[1]);
                mma16816(o[2 * g + 1], ph, vh[2], vh[3]);
                mma16816(o[2 * g + 1], ph, vl[2], vl[3]);
                mma16816(o[2 * g + 1], pl, vh[2], vh[3]);
            }
        }
        __syncthreads();
    }

    const float inv0 = 1.f / l_[0];
    const float inv1 = 1.f / l_[1];
    const int r0 = q0 + wid * 16 + (lane >> 2);
    const int cb = h * 64 + (lane & 3) * 2;
    const size_t tok = (size_t)b * SQL;
#pragma unroll
    for (int nd = 0; nd < 8; ++nd) {
        int c = cb + nd * 8;
        uint32_t hh, ll;
        split2(o[nd][0] * inv0, o[nd][1] * inv0, hh, ll);
        *(uint32_t*)&g_aoh[(tok + r0) * EMBED + c] = hh;
        *(uint32_t*)&g_aol[(tok + r0) * EMBED + c] = ll;
        split2(o[nd][2] * inv1, o[nd][3] * inv1, hh, ll);
        *(uint32_t*)&g_aoh[(tok + r0 + 8) * EMBED + c] = hh;
        *(uint32_t*)&g_aol[(tok + r0 + 8) * EMBED + c] = ll;
    }
}

// ---------------------------------------------------------------------------
// Launch
// ---------------------------------------------------------------------------
extern "C" void kernel_launch(void* const* d_in, const int* in_sizes, int n_in,
                              void* d_out, int out_size)
{
    const float* x   = (const float*)d_in[0];
    const float* ctx = (const float*)d_in[1];
    const float* Wq  = (const float*)d_in[2];
    const float* bq  = (const float*)d_in[3];
    const float* Wk  = (const float*)d_in[4];
    const float* bk  = (const float*)d_in[5];
    const float* Wv  = (const float*)d_in[6];
    const float* bv  = (const float*)d_in[7];
    const float* Wp  = (const float*)d_in[8];
    const float* bp  = (const float*)d_in[9];
    float* out = (float*)d_out;

    __nv_bfloat16 *Qh, *Ql, *Kh, *Kl, *Vh, *Vl, *xh, *xl, *ch_, *cl_, *aoh, *aol;
    __nv_bfloat16 *WqTh, *WqTl, *WkTh, *WkTl, *WvTh, *WvTl, *WpTh, *WpTl;
    cudaGetSymbolAddress((void**)&Qh,  g_Qh);
    cudaGetSymbolAddress((void**)&Ql,  g_Ql);
    cudaGetSymbolAddress((void**)&Kh,  g_Kh);
    cudaGetSymbolAddress((void**)&Kl,  g_Kl);
    cudaGetSymbolAddress((void**)&Vh,  g_Vh);
    cudaGetSymbolAddress((void**)&Vl,  g_Vl);
    cudaGetSymbolAddress((void**)&xh,  g_xh);
    cudaGetSymbolAddress((void**)&xl,  g_xl);
    cudaGetSymbolAddress((void**)&ch_, g_ch);
    cudaGetSymbolAddress((void**)&cl_, g_cl);
    cudaGetSymbolAddress((void**)&aoh, g_aoh);
    cudaGetSymbolAddress((void**)&aol, g_aol);
    cudaGetSymbolAddress((void**)&WqTh, g_WqTh);
    cudaGetSymbolAddress((void**)&WqTl, g_WqTl);
    cudaGetSymbolAddress((void**)&WkTh, g_WkTh);
    cudaGetSymbolAddress((void**)&WkTl, g_WkTl);
    cudaGetSymbolAddress((void**)&WvTh, g_WvTh);
    cudaGetSymbolAddress((void**)&WvTl, g_WvTl);
    cudaGetSymbolAddress((void**)&WpTh, g_WpTh);
    cudaGetSymbolAddress((void**)&WpTl, g_WpTl);

    cudaFuncSetAttribute(gemm_qkv,
                         cudaFuncAttributeMaxDynamicSharedMemorySize, GEMM_SMEM);
    cudaFuncSetAttribute(gemm_out,
                         cudaFuncAttributeMaxDynamicSharedMemorySize, GEMM_SMEM);
    cudaFuncSetAttribute(flash_mma,
                         cudaFuncAttributeMaxDynamicSharedMemorySize, FLASH_SMEM);

    const int NX = BATCH * SQL  * EMBED;
    const int NC = BATCH * SKVL * EMBED;

    // Split inputs
    split_f32<<<(NX / 4 + 255) / 256, 256>>>((const float4*)x,   xh,  xl,  NX / 4);
    split_f32<<<(NC / 4 + 255) / 256, 256>>>((const float4*)ctx, ch_, cl_, NC / 4);

    // Transpose+split weights (3 fused EMBED sets + the VOCAB one)
    TArgs ta;
    ta.s[0] = {Wq, WqTh, WqTl};
    ta.s[1] = {Wk, WkTh, WkTl};
    ta.s[2] = {Wv, WvTh, WvTl};
    transpose_split3<<<dim3(EMBED / 32, EMBED / 32, 3), dim3(32, 8)>>>(ta, EMBED, EMBED);
    transpose_split<<<dim3(VOCAB / 32, EMBED / 32), dim3(32, 8)>>>(Wp, WpTh, WpTl, EMBED, VOCAB);

    // Fused Q/K/V projections -> pre-split bf16 hi/lo
    QKVArgs qa;
    qa.s[0] = {xh,  xl,  WqTh, WqTl, bq, Qh, Ql};
    qa.s[1] = {ch_, cl_, WkTh, WkTl, bk, Kh, Kl};
    qa.s[2] = {ch_, cl_, WvTh, WvTl, bv, Vh, Vl};
    gemm_qkv<<<dim3(EMBED / 128, (BATCH * SKVL) / 128, 3), 256, GEMM_SMEM>>>(qa);

    // Tensor-core flash attention -> pre-split AO hi/lo
    flash_mma<<<dim3(SQL / 128, BATCH * NHEADS), 256, FLASH_SMEM>>>();

    // Output projection
    gemm_out<<<dim3(VOCAB / 128, (BATCH * SQL) / 128), 256, GEMM_SMEM>>>(
        aoh, aol, WpTh, WpTl, bp, out, VOCAB, EMBED);
}